// round 4
// baseline (speedup 1.0000x reference)
#include <cuda_runtime.h>
#include <math.h>

#define NN 100000
#define NE 3200000
#define EBLK ((NE + 255) / 256)
#define NBLK ((NN + 255) / 256)
#define SCAN_BLKS 196   // 196*512 = 100352 >= NN

// ---------------- scratch ---------------------------------------------------
__device__ float g_tmpA[NN * 8];
__device__ float g_tmpB[NN * 8];
__device__ int2  g_edge[NE];     // {src, dst}
__device__ int2  g_rec[NE];      // CSR-sorted {src, w_bits}
__device__ int   g_cnt[NN];      // per-dst degree
__device__ int   g_off[NN];      // exclusive offsets
__device__ int   g_pos[NN];      // running scatter cursor
__device__ int   g_bsum[256];
__device__ int   g_bsumx[256];
__device__ int   g_is64;

// ---------------- f32x2 helpers --------------------------------------------
__device__ __forceinline__ unsigned long long bcast2(float x) {
    unsigned long long r;
    unsigned u = __float_as_uint(x);
    asm("mov.b64 %0, {%1, %1};" : "=l"(r) : "r"(u));
    return r;
}
__device__ __forceinline__ void ffma2(unsigned long long& d,
                                      unsigned long long a, unsigned long long b) {
    asm("fma.rn.f32x2 %0, %1, %2, %0;" : "+l"(d) : "l"(a), "l"(b));
}
__device__ __forceinline__ void unpack2(unsigned long long v, float& lo, float& hi) {
    asm("mov.b64 {%0, %1}, %2;" : "=f"(lo), "=f"(hi) : "l"(v));
}

// ---------------- detect int64 vs int32 edge_index -------------------------
__global__ void detect_kernel(const unsigned int* __restrict__ w) {
    unsigned v = w[threadIdx.x * 2 + 1];
    int any = __syncthreads_or(v != 0u);
    if (threadIdx.x == 0) g_is64 = any ? 0 : 1;
}

__global__ void zero_k() {
    int i = blockIdx.x * blockDim.x + threadIdx.x;
    if (i < NN) g_cnt[i] = 0;
}

// convert + histogram of dst
__global__ void hist_convert(const void* __restrict__ edge_index) {
    int e = blockIdx.x * blockDim.x + threadIdx.x;
    if (e >= NE) return;
    int s, d;
    if (g_is64) {
        const long long* p = (const long long*)edge_index;
        s = (int)p[e]; d = (int)p[NE + e];
    } else {
        const int* p = (const int*)edge_index;
        s = p[e]; d = p[NE + e];
    }
    g_edge[e] = make_int2(s, d);
    atomicAdd(&g_cnt[d], 1);
}

// ---------------- 3-kernel exclusive prefix scan ---------------------------
__device__ __forceinline__ int block_incl_scan(int v, int tid) {
    __shared__ int wsum[8];
    int lane = tid & 31, w = tid >> 5;
#pragma unroll
    for (int d = 1; d < 32; d <<= 1) {
        int t = __shfl_up_sync(0xffffffffu, v, d);
        if (lane >= d) v += t;
    }
    if (lane == 31) wsum[w] = v;
    __syncthreads();
    if (w == 0) {
        int s = (lane < 8) ? wsum[lane] : 0;
#pragma unroll
        for (int d = 1; d < 8; d <<= 1) {
            int t = __shfl_up_sync(0xffffffffu, s, d);
            if (lane >= d) s += t;
        }
        if (lane < 8) wsum[lane] = s;
    }
    __syncthreads();
    return v + ((w > 0) ? wsum[w - 1] : 0);
}

__global__ void scanA() {
    int t = threadIdx.x;
    int i0 = blockIdx.x * 512 + 2 * t, i1 = i0 + 1;
    int a = (i0 < NN) ? g_cnt[i0] : 0;
    int b = (i1 < NN) ? g_cnt[i1] : 0;
    int p = a + b;
    int incl = block_incl_scan(p, t);
    int excl = incl - p;
    if (i0 < NN) g_off[i0] = excl;
    if (i1 < NN) g_off[i1] = excl + a;
    if (t == 255) g_bsum[blockIdx.x] = incl;
}

__global__ void scanB() {
    int t = threadIdx.x;
    int v = (t < SCAN_BLKS) ? g_bsum[t] : 0;
    int incl = block_incl_scan(v, t);
    if (t < SCAN_BLKS) g_bsumx[t] = incl - v;
}

__global__ void scanC() {
    int t = threadIdx.x;
    int add = g_bsumx[blockIdx.x];
    int i0 = blockIdx.x * 512 + 2 * t, i1 = i0 + 1;
    if (i0 < NN) { int o = g_off[i0] + add; g_off[i0] = o; g_pos[i0] = o; }
    if (i1 < NN) { int o = g_off[i1] + add; g_off[i1] = o; g_pos[i1] = o; }
}

// scatter edges into CSR order
__global__ void scatter_k(const float* __restrict__ ew) {
    int e = blockIdx.x * blockDim.x + threadIdx.x;
    if (e >= NE) return;
    int2 sd = g_edge[e];
    float w = ew[e];
    int p = atomicAdd(&g_pos[sd.y], 1);
    g_rec[p] = make_int2(sd.x, __float_as_int(w));
}

// ---------------- layer-1: g_tmpA = x @ W1 (512 -> 8) ----------------------
__global__ void l1_kernel(const float* __restrict__ x, const float* __restrict__ W1) {
    __shared__ float raw[4096];                                  // 16 KB
    __shared__ __align__(16) unsigned long long sh2[2048];       // 16 KB: [p][k]
    const int tid = threadIdx.x;

#pragma unroll
    for (int i = 0; i < 4; i++)
        ((float4*)raw)[tid + i * 256] = __ldg(((const float4*)W1) + tid + i * 256);
    __syncthreads();

#pragma unroll
    for (int i = tid; i < 2048; i += 256) {
        int idx = ((i & 3) << 9) | (i >> 2);
        int p = idx >> 9, k = idx & 511;
        unsigned lo = __float_as_uint(raw[k * 8 + 2 * p]);
        unsigned hi = __float_as_uint(raw[k * 8 + 2 * p + 1]);
        unsigned long long v;
        asm("mov.b64 %0, {%1, %2};" : "=l"(v) : "r"(lo), "r"(hi));
        sh2[idx] = v;
    }
    __syncthreads();

    const int lane = tid & 31;
    const int warp = tid >> 5;
    const int g = lane >> 3;
    const int r = lane & 7;
    const int node = blockIdx.x * 32 + warp * 4 + g;

    const float* xrow = x + (size_t)node * 512;
    unsigned long long acc[4];
#pragma unroll
    for (int p = 0; p < 4; p++) acc[p] = 0ull;

#pragma unroll 4
    for (int i = 0; i < 16; i++) {
        int kbase = i * 32 + r * 4;
        float4 xv = __ldg((const float4*)(xrow + kbase));
        unsigned long long x0 = bcast2(xv.x), x1 = bcast2(xv.y);
        unsigned long long x2 = bcast2(xv.z), x3 = bcast2(xv.w);
#pragma unroll
        for (int p = 0; p < 4; p++) {
            const ulonglong2* wp = (const ulonglong2*)&sh2[p * 512 + kbase];
            ulonglong2 wA = wp[0];
            ulonglong2 wB = wp[1];
            ffma2(acc[p], x0, wA.x);
            ffma2(acc[p], x1, wA.y);
            ffma2(acc[p], x2, wB.x);
            ffma2(acc[p], x3, wB.y);
        }
    }

    float s[8];
#pragma unroll
    for (int p = 0; p < 4; p++) unpack2(acc[p], s[2 * p], s[2 * p + 1]);
#pragma unroll
    for (int d = 1; d < 8; d <<= 1) {
#pragma unroll
        for (int o = 0; o < 8; o++)
            s[o] += __shfl_xor_sync(0xffffffffu, s[o], d);
    }
    if (r == 0) {
        float4* t = (float4*)(g_tmpA + (size_t)node * 8);
        t[0] = make_float4(s[0], s[1], s[2], s[3]);
        t[1] = make_float4(s[4], s[5], s[6], s[7]);
    }
}

// ---------------- fused gather-aggregate + epilogue ------------------------
// 8-lane subwarp per node (4 nodes/warp). Each lane handles every-8th edge:
// short dependent chains, ~24 independent loads in flight per warp.
// POST: 1 = relu(acc+bias) ; 2 = relu(acc@Wa+bias)@Wb ; 4 = log_softmax(acc@Wa+bias)
template <int POST, bool AB>
__global__ void agg_k(const float* __restrict__ bias,
                      const float* __restrict__ Wa,
                      const float* __restrict__ Wb,
                      float* __restrict__ out) {
    const int tid  = threadIdx.x;
    const int lane = tid & 31;
    const int warp = tid >> 5;
    const int g    = lane >> 3;
    const int r    = lane & 7;
    const int n = blockIdx.x * 32 + warp * 4 + g;   // NN = 3125*32 exactly

    const float* fin = AB ? g_tmpA : g_tmpB;
    float*      fout = AB ? g_tmpB : g_tmpA;

    const int base = g_off[n];
    const int cnt  = g_cnt[n];

    float acc[8];
#pragma unroll
    for (int o = 0; o < 8; o++) acc[o] = 0.f;

    for (int i = r; i < cnt; i += 8) {
        int2 rec = __ldg(&g_rec[base + i]);
        const float4* p = (const float4*)(fin + (size_t)rec.x * 8);
        float4 u0 = __ldg(p);
        float4 u1 = __ldg(p + 1);
        float w = __int_as_float(rec.y);
        acc[0] += w * u0.x; acc[1] += w * u0.y; acc[2] += w * u0.z; acc[3] += w * u0.w;
        acc[4] += w * u1.x; acc[5] += w * u1.y; acc[6] += w * u1.z; acc[7] += w * u1.w;
    }

    // butterfly reduce within 8-lane group
#pragma unroll
    for (int d = 1; d < 8; d <<= 1) {
#pragma unroll
        for (int o = 0; o < 8; o++)
            acc[o] += __shfl_xor_sync(0xffffffffu, acc[o], d);
    }

    if (r != 0) return;

    if (POST == 1) {
        float4* t = (float4*)(fout + (size_t)n * 8);
        t[0] = make_float4(fmaxf(acc[0] + __ldg(&bias[0]), 0.f),
                           fmaxf(acc[1] + __ldg(&bias[1]), 0.f),
                           fmaxf(acc[2] + __ldg(&bias[2]), 0.f),
                           fmaxf(acc[3] + __ldg(&bias[3]), 0.f));
        t[1] = make_float4(fmaxf(acc[4] + __ldg(&bias[4]), 0.f),
                           fmaxf(acc[5] + __ldg(&bias[5]), 0.f),
                           fmaxf(acc[6] + __ldg(&bias[6]), 0.f),
                           fmaxf(acc[7] + __ldg(&bias[7]), 0.f));
    } else if (POST == 2) {
        float m[16];
#pragma unroll
        for (int o = 0; o < 16; o++) m[o] = __ldg(&bias[o]);
#pragma unroll
        for (int j = 0; j < 8; j++) {
            float hj = acc[j];
#pragma unroll
            for (int o = 0; o < 16; o++) m[o] += hj * __ldg(&Wa[j * 16 + o]);
        }
#pragma unroll
        for (int o = 0; o < 16; o++) m[o] = fmaxf(m[o], 0.f);
        float rr[8];
#pragma unroll
        for (int o = 0; o < 8; o++) rr[o] = 0.f;
#pragma unroll
        for (int j = 0; j < 16; j++) {
            float mj = m[j];
#pragma unroll
            for (int o = 0; o < 8; o++) rr[o] += mj * __ldg(&Wb[j * 8 + o]);
        }
        float4* t = (float4*)(fout + (size_t)n * 8);
        t[0] = make_float4(rr[0], rr[1], rr[2], rr[3]);
        t[1] = make_float4(rr[4], rr[5], rr[6], rr[7]);
    } else {  // POST == 4
        float v[10];
#pragma unroll
        for (int o = 0; o < 10; o++) v[o] = __ldg(&bias[o]);
#pragma unroll
        for (int j = 0; j < 8; j++) {
            float hj = acc[j];
#pragma unroll
            for (int o = 0; o < 10; o++) v[o] += hj * __ldg(&Wa[j * 10 + o]);
        }
        float mx = -1e30f;
#pragma unroll
        for (int o = 0; o < 10; o++) mx = fmaxf(mx, v[o]);
        float sum = 0.f;
#pragma unroll
        for (int o = 0; o < 10; o++) sum += expf(v[o] - mx);
        float l = logf(sum);
#pragma unroll
        for (int o = 0; o < 10; o++) out[(size_t)n * 10 + o] = v[o] - mx - l;
    }
}

// ---------------- launch ---------------------------------------------------
extern "C" void kernel_launch(void* const* d_in, const int* in_sizes, int n_in,
                              void* d_out, int out_size) {
    const float* x  = (const float*)d_in[0];
    const void*  ei = d_in[1];
    const float* ew = (const float*)d_in[2];
    const float* W1 = (const float*)d_in[3];
    const float* b1 = (const float*)d_in[4];
    const float* W2 = (const float*)d_in[5];
    const float* b2 = (const float*)d_in[6];
    const float* W3 = (const float*)d_in[7];
    const float* b3 = (const float*)d_in[8];
    const float* W4 = (const float*)d_in[9];
    const float* b4 = (const float*)d_in[10];
    float* out = (float*)d_out;

    detect_kernel<<<1, 256>>>((const unsigned int*)ei);
    zero_k<<<NBLK, 256>>>();
    hist_convert<<<EBLK, 256>>>(ei);
    scanA<<<SCAN_BLKS, 256>>>();
    scanB<<<1, 256>>>();
    scanC<<<SCAN_BLKS, 256>>>();
    scatter_k<<<EBLK, 256>>>(ew);

    l1_kernel<<<NN / 32, 256>>>(x, W1);                            // tmpA = x@W1

    agg_k<1, true ><<<NN / 32, 256>>>(b1, nullptr, nullptr, nullptr); // B = relu(A@tmpA + b1)
    agg_k<2, false><<<NN / 32, 256>>>(b2, W2, W3, nullptr);           // A = relu((A@B)W2 + b2)W3
    agg_k<1, true ><<<NN / 32, 256>>>(b3, nullptr, nullptr, nullptr); // B = relu(A@tA + b3)
    agg_k<4, false><<<NN / 32, 256>>>(b4, W4, nullptr, out);          // out = lsm((A@B)W4 + b4)
}

// round 6
// speedup vs baseline: 1.0189x; 1.0189x over previous
#include <cuda_runtime.h>
#include <math.h>

#define NN 100000
#define NE 3200000
#define EBLK ((NE + 255) / 256)
#define NBLK ((NN + 255) / 256)

// ---------------- scratch ---------------------------------------------------
__device__ float g_tmp[NN * 8];
__device__ float g_agg[NN * 8];
__device__ int2  g_edge[NE];
__device__ int   g_is64;

// ---------------- f32x2 helpers --------------------------------------------
__device__ __forceinline__ unsigned long long bcast2(float x) {
    unsigned long long r;
    unsigned u = __float_as_uint(x);
    asm("mov.b64 %0, {%1, %1};" : "=l"(r) : "r"(u));
    return r;
}
__device__ __forceinline__ void ffma2(unsigned long long& d,
                                      unsigned long long a, unsigned long long b) {
    asm("fma.rn.f32x2 %0, %1, %2, %0;" : "+l"(d) : "l"(a), "l"(b));
}
__device__ __forceinline__ void unpack2(unsigned long long v, float& lo, float& hi) {
    asm("mov.b64 {%0, %1}, %2;" : "=f"(lo), "=f"(hi) : "l"(v));
}

// ---------------- vector reduction (sm_90+) --------------------------------
__device__ __forceinline__ void red4(float* p, float a, float b, float c, float d) {
    asm volatile("red.global.add.v4.f32 [%0], {%1,%2,%3,%4};"
                 :: "l"(p), "f"(a), "f"(b), "f"(c), "f"(d) : "memory");
}

// ---------------- detect int64 vs int32 edge_index -------------------------
__global__ void detect_kernel(const unsigned int* __restrict__ w) {
    unsigned v = w[threadIdx.x * 2 + 1];
    int any = __syncthreads_or(v != 0u);
    if (threadIdx.x == 0) g_is64 = any ? 0 : 1;
}

__global__ void convert_kernel(const void* __restrict__ edge_index) {
    int e = blockIdx.x * blockDim.x + threadIdx.x;
    if (e >= NE) return;
    int s, d;
    if (g_is64) {
        const long long* p = (const long long*)edge_index;
        s = (int)p[e]; d = (int)p[NE + e];
    } else {
        const int* p = (const int*)edge_index;
        s = p[e]; d = p[NE + e];
    }
    g_edge[e] = make_int2(s, d);
}

// ---------------- layer-1: g_tmp = x @ W1 (512 -> 8); zero g_agg -----------
// 8-lane subwarps per node (4 nodes/warp, 32 nodes/block). x loaded straight
// from global (coalesced 128B per group, no staging). W1 staged once in shared
// as transposed f32-pairs; packed f32x2 FMA; 3-step butterfly reduce.
__global__ void l1_kernel(const float* __restrict__ x, const float* __restrict__ W1) {
    __shared__ float raw[4096];                                  // 16 KB
    __shared__ __align__(16) unsigned long long sh2[2048];       // 16 KB: [p][k]
    const int tid = threadIdx.x;

#pragma unroll
    for (int i = 0; i < 4; i++)
        ((float4*)raw)[tid + i * 256] = __ldg(((const float4*)W1) + tid + i * 256);
    __syncthreads();

#pragma unroll
    for (int i = tid; i < 2048; i += 256) {
        int idx = ((i & 3) << 9) | (i >> 2);
        int p = idx >> 9, k = idx & 511;
        unsigned lo = __float_as_uint(raw[k * 8 + 2 * p]);
        unsigned hi = __float_as_uint(raw[k * 8 + 2 * p + 1]);
        unsigned long long v;
        asm("mov.b64 %0, {%1, %2};" : "=l"(v) : "r"(lo), "r"(hi));
        sh2[idx] = v;
    }
    __syncthreads();

    const int lane = tid & 31;
    const int warp = tid >> 5;
    const int g = lane >> 3;
    const int r = lane & 7;
    const int node = blockIdx.x * 32 + warp * 4 + g;   // NN divisible by 32

    const float* xrow = x + (size_t)node * 512;
    unsigned long long acc[4];
#pragma unroll
    for (int p = 0; p < 4; p++) acc[p] = 0ull;

#pragma unroll 4
    for (int i = 0; i < 16; i++) {
        int kbase = i * 32 + r * 4;
        float4 xv = __ldg((const float4*)(xrow + kbase));
        unsigned long long x0 = bcast2(xv.x), x1 = bcast2(xv.y);
        unsigned long long x2 = bcast2(xv.z), x3 = bcast2(xv.w);
#pragma unroll
        for (int p = 0; p < 4; p++) {
            const ulonglong2* wp = (const ulonglong2*)&sh2[p * 512 + kbase];
            ulonglong2 wA = wp[0];
            ulonglong2 wB = wp[1];
            ffma2(acc[p], x0, wA.x);
            ffma2(acc[p], x1, wA.y);
            ffma2(acc[p], x2, wB.x);
            ffma2(acc[p], x3, wB.y);
        }
    }

    float s[8];
#pragma unroll
    for (int p = 0; p < 4; p++) unpack2(acc[p], s[2 * p], s[2 * p + 1]);
#pragma unroll
    for (int d = 1; d < 8; d <<= 1) {
#pragma unroll
        for (int o = 0; o < 8; o++)
            s[o] += __shfl_xor_sync(0xffffffffu, s[o], d);
    }
    if (r == 0) {
        float4* t = (float4*)(g_tmp + (size_t)node * 8);
        t[0] = make_float4(s[0], s[1], s[2], s[3]);
        t[1] = make_float4(s[4], s[5], s[6], s[7]);
        float4 z = make_float4(0.f, 0.f, 0.f, 0.f);
        float4* a = (float4*)(g_agg + (size_t)node * 8);
        a[0] = z; a[1] = z;
    }
}

// ---------------- edge scatter (8-wide): agg[dst] += tmp[src] * w ----------
__global__ void edge_k(const float* __restrict__ w) {
    int e = blockIdx.x * blockDim.x + threadIdx.x;
    if (e >= NE) return;
    int2 sd = __ldg(&g_edge[e]);
    float wt = __ldg(&w[e]);
    const float4* ts = (const float4*)(g_tmp + (size_t)sd.x * 8);
    float* ad = g_agg + (size_t)sd.y * 8;
    float4 a = __ldg(ts);
    float4 b = __ldg(ts + 1);
    red4(ad,     a.x * wt, a.y * wt, a.z * wt, a.w * wt);
    red4(ad + 4, b.x * wt, b.y * wt, b.z * wt, b.w * wt);
}

// ---------------- elementwise: tmp = relu(agg + b), zero agg ---------------
__global__ void trelu(const float* __restrict__ b) {
    int n = blockIdx.x * blockDim.x + threadIdx.x;
    if (n >= NN) return;
    float4* arow = (float4*)(g_agg + (size_t)n * 8);
    float4* trow = (float4*)(g_tmp + (size_t)n * 8);
    float4 v0 = arow[0], v1 = arow[1];
    trow[0] = make_float4(fmaxf(v0.x + __ldg(&b[0]), 0.f),
                          fmaxf(v0.y + __ldg(&b[1]), 0.f),
                          fmaxf(v0.z + __ldg(&b[2]), 0.f),
                          fmaxf(v0.w + __ldg(&b[3]), 0.f));
    trow[1] = make_float4(fmaxf(v1.x + __ldg(&b[4]), 0.f),
                          fmaxf(v1.y + __ldg(&b[5]), 0.f),
                          fmaxf(v1.z + __ldg(&b[6]), 0.f),
                          fmaxf(v1.w + __ldg(&b[7]), 0.f));
    float4 z = make_float4(0.f, 0.f, 0.f, 0.f);
    arow[0] = z; arow[1] = z;
}

// ---------------- fused mid: tmp = relu(agg@W2 + b2) @ W3, zero agg --------
__global__ void tmid(const float* __restrict__ W2, const float* __restrict__ b2,
                     const float* __restrict__ W3) {
    int n = blockIdx.x * blockDim.x + threadIdx.x;
    if (n >= NN) return;
    float4* arow = (float4*)(g_agg + (size_t)n * 8);
    float4 v0 = arow[0], v1 = arow[1];
    float h[8] = {v0.x, v0.y, v0.z, v0.w, v1.x, v1.y, v1.z, v1.w};
    float4 z = make_float4(0.f, 0.f, 0.f, 0.f);
    arow[0] = z; arow[1] = z;

    float m[16];
#pragma unroll
    for (int o = 0; o < 16; o++) m[o] = __ldg(&b2[o]);
#pragma unroll
    for (int j = 0; j < 8; j++) {
        float hj = h[j];
#pragma unroll
        for (int o = 0; o < 16; o++)
            m[o] += hj * __ldg(&W2[j * 16 + o]);
    }
#pragma unroll
    for (int o = 0; o < 16; o++) m[o] = fmaxf(m[o], 0.f);

    float acc[8];
#pragma unroll
    for (int o = 0; o < 8; o++) acc[o] = 0.f;
#pragma unroll
    for (int j = 0; j < 16; j++) {
        float mj = m[j];
#pragma unroll
        for (int o = 0; o < 8; o++)
            acc[o] += mj * __ldg(&W3[j * 8 + o]);
    }
    float4* trow = (float4*)(g_tmp + (size_t)n * 8);
    trow[0] = make_float4(acc[0], acc[1], acc[2], acc[3]);
    trow[1] = make_float4(acc[4], acc[5], acc[6], acc[7]);
}

// ---------------- final: out = log_softmax(agg@W4 + b4) --------------------
__global__ void lsm_kernel(const float* __restrict__ W4, const float* __restrict__ b4,
                           float* __restrict__ out) {
    int n = blockIdx.x * blockDim.x + threadIdx.x;
    if (n >= NN) return;
    const float4* arow = (const float4*)(g_agg + (size_t)n * 8);
    float4 v0 = __ldg(arow), v1 = __ldg(arow + 1);
    float h[8] = {v0.x, v0.y, v0.z, v0.w, v1.x, v1.y, v1.z, v1.w};

    float v[10];
#pragma unroll
    for (int o = 0; o < 10; o++) v[o] = __ldg(&b4[o]);
#pragma unroll
    for (int j = 0; j < 8; j++) {
        float hj = h[j];
#pragma unroll
        for (int o = 0; o < 10; o++)
            v[o] += hj * __ldg(&W4[j * 10 + o]);
    }
    float m = -1e30f;
#pragma unroll
    for (int o = 0; o < 10; o++) m = fmaxf(m, v[o]);
    float s = 0.f;
#pragma unroll
    for (int o = 0; o < 10; o++) s += expf(v[o] - m);
    float l = logf(s);
#pragma unroll
    for (int o = 0; o < 10; o++) out[(size_t)n * 10 + o] = v[o] - m - l;
}

// ---------------- launch ---------------------------------------------------
extern "C" void kernel_launch(void* const* d_in, const int* in_sizes, int n_in,
                              void* d_out, int out_size) {
    const float* x  = (const float*)d_in[0];
    const void*  ei = d_in[1];
    const float* ew = (const float*)d_in[2];
    const float* W1 = (const float*)d_in[3];
    const float* b1 = (const float*)d_in[4];
    const float* W2 = (const float*)d_in[5];
    const float* b2 = (const float*)d_in[6];
    const float* W3 = (const float*)d_in[7];
    const float* b3 = (const float*)d_in[8];
    const float* W4 = (const float*)d_in[9];
    const float* b4 = (const float*)d_in[10];
    float* out = (float*)d_out;

    detect_kernel<<<1, 256>>>((const unsigned int*)ei);
    convert_kernel<<<EBLK, 256>>>(ei);

    l1_kernel<<<NN / 32, 256>>>(x, W1);   // tmp = x@W1, agg zeroed
    edge_k<<<EBLK, 256>>>(ew);            // agg1 = A @ (x W1)

    trelu<<<NBLK, 256>>>(b1);             // tmp = relu(agg1 + b1), agg zeroed
    edge_k<<<EBLK, 256>>>(ew);            // agg2 = A @ relu1

    tmid<<<NBLK, 256>>>(W2, b2, W3);      // tmp = relu(agg2 W2 + b2) W3, agg zeroed
    edge_k<<<EBLK, 256>>>(ew);            // agg3 = A @ (relu2 W3)

    trelu<<<NBLK, 256>>>(b3);             // tmp = relu(agg3 + b3), agg zeroed
    edge_k<<<EBLK, 256>>>(ew);            // agg4 = A @ relu3

    lsm_kernel<<<NBLK, 256>>>(W4, b4, out);
}